// round 1
// baseline (speedup 1.0000x reference)
#include <cuda_runtime.h>
#include <cstdint>

// GCN block: agg = D_in^-1/2 * A * (D_out^-1/2 * x); h = agg@W + b;
// h = nodenorm(h); out = relu(h) + x.
// N = 100000, E = 1600000, D = 128 (shapes fixed by the dataset).

#define DIMF 128
#define MAXN 100352

// Scratch (device globals — allocation-free per harness rules)
__device__ float g_deg_out[MAXN];
__device__ float g_deg_in[MAXN];
__device__ float g_agg[MAXN * DIMF];

// ---------------------------------------------------------------------------
// K1: zero agg + degree arrays
// ---------------------------------------------------------------------------
__global__ void zero_kernel(int N) {
    int i = blockIdx.x * blockDim.x + threadIdx.x;
    int total4 = N * (DIMF / 4);
    if (i < total4)
        reinterpret_cast<float4*>(g_agg)[i] = make_float4(0.f, 0.f, 0.f, 0.f);
    if (i < N) {
        g_deg_out[i] = 0.f;
        g_deg_in[i] = 0.f;
    }
}

// ---------------------------------------------------------------------------
// K2: degrees via float atomics (exact for counts < 2^24)
// ---------------------------------------------------------------------------
__global__ void deg_kernel(const int* __restrict__ src, const int* __restrict__ dst, int E) {
    int e = blockIdx.x * blockDim.x + threadIdx.x;
    if (e < E) {
        atomicAdd(&g_deg_out[src[e]], 1.0f);
        atomicAdd(&g_deg_in[dst[e]], 1.0f);
    }
}

// ---------------------------------------------------------------------------
// K3: edge aggregation. One warp per edge: 32 lanes x float4 = 128 floats.
// Gather x[src]*rsqrt(max(deg_out,1)), vector-red into agg[dst].
// red.global.add.v4.f32: one 16B L2 reduction per lane, no return traffic.
// ---------------------------------------------------------------------------
__global__ void agg_kernel(const float4* __restrict__ x4,
                           const int* __restrict__ src,
                           const int* __restrict__ dst, int E) {
    int w = blockIdx.x * (blockDim.x >> 5) + (threadIdx.x >> 5);
    if (w >= E) return;
    int lane = threadIdx.x & 31;
    int s = src[w];   // broadcast LDG (all lanes same address)
    int d = dst[w];
    float ns = rsqrtf(fmaxf(g_deg_out[s], 1.0f));
    float4 v = x4[s * (DIMF / 4) + lane];
    v.x *= ns; v.y *= ns; v.z *= ns; v.w *= ns;
    float* p = g_agg + (size_t)d * DIMF + lane * 4;
    asm volatile("red.global.add.v4.f32 [%0], {%1, %2, %3, %4};"
                 :: "l"(p), "f"(v.x), "f"(v.y), "f"(v.z), "f"(v.w)
                 : "memory");
}

// ---------------------------------------------------------------------------
// K4: fused  h = (agg * norm_dst) @ W + b ; NodeNorm ; relu ; + x.
// Persistent blocks, W resident in smem (64KB), 4 rows per warp so each
// W smem read (16B) feeds 16 FMAs. Lane j owns output columns 4j..4j+3.
// ---------------------------------------------------------------------------
#define GEMM_SMEM_BYTES ((DIMF * DIMF + 8 * 4 * DIMF) * 4)   // 81920

__global__ __launch_bounds__(256, 2)
void gemm_norm_kernel(const float4* __restrict__ x4,
                      const float* __restrict__ weight,
                      const float* __restrict__ bias,
                      float4* __restrict__ out4, int N) {
    extern __shared__ float sh[];
    float* Wsh = sh;                      // 128x128 f32
    float* rowbuf = sh + DIMF * DIMF;     // 8 warps * 4 rows * 128 f32

    // cooperative W load (global is L2-resident after first block)
    {
        const float4* Wg = reinterpret_cast<const float4*>(weight);
        float4* Ws = reinterpret_cast<float4*>(Wsh);
        for (int i = threadIdx.x; i < DIMF * DIMF / 4; i += blockDim.x)
            Ws[i] = Wg[i];
    }
    __syncthreads();

    const int warp = threadIdx.x >> 5;
    const int lane = threadIdx.x & 31;
    const int nwarps = (gridDim.x * blockDim.x) >> 5;
    const int gwarp = (blockIdx.x * blockDim.x + threadIdx.x) >> 5;
    float* myrow = rowbuf + warp * (4 * DIMF);
    const float4* Wv = reinterpret_cast<const float4*>(Wsh);
    const float4 bv = reinterpret_cast<const float4*>(bias)[lane];

    for (int base = gwarp * 4; base < N; base += nwarps * 4) {
        // load up to 4 rows of agg, scaled by norm_dst, into per-warp smem
        #pragma unroll
        for (int r = 0; r < 4; r++) {
            int row = base + r;
            if (row < N) {
                float nd = rsqrtf(fmaxf(g_deg_in[row], 1.0f));
                float4 a = reinterpret_cast<const float4*>(g_agg)[row * (DIMF / 4) + lane];
                a.x *= nd; a.y *= nd; a.z *= nd; a.w *= nd;
                reinterpret_cast<float4*>(myrow + r * DIMF)[lane] = a;
            }
        }
        __syncwarp();

        float4 acc0 = {0,0,0,0}, acc1 = {0,0,0,0}, acc2 = {0,0,0,0}, acc3 = {0,0,0,0};

        #pragma unroll 4
        for (int k4 = 0; k4 < DIMF / 4; k4++) {
            float4 a0 = reinterpret_cast<const float4*>(myrow + 0 * DIMF)[k4];
            float4 a1 = reinterpret_cast<const float4*>(myrow + 1 * DIMF)[k4];
            float4 a2 = reinterpret_cast<const float4*>(myrow + 2 * DIMF)[k4];
            float4 a3 = reinterpret_cast<const float4*>(myrow + 3 * DIMF)[k4];
            const float* p0 = reinterpret_cast<const float*>(&a0);
            const float* p1 = reinterpret_cast<const float*>(&a1);
            const float* p2 = reinterpret_cast<const float*>(&a2);
            const float* p3 = reinterpret_cast<const float*>(&a3);
            #pragma unroll
            for (int j = 0; j < 4; j++) {
                float4 w = Wv[(k4 * 4 + j) * (DIMF / 4) + lane];
                float c0 = p0[j], c1 = p1[j], c2 = p2[j], c3 = p3[j];
                acc0.x = fmaf(c0, w.x, acc0.x); acc0.y = fmaf(c0, w.y, acc0.y);
                acc0.z = fmaf(c0, w.z, acc0.z); acc0.w = fmaf(c0, w.w, acc0.w);
                acc1.x = fmaf(c1, w.x, acc1.x); acc1.y = fmaf(c1, w.y, acc1.y);
                acc1.z = fmaf(c1, w.z, acc1.z); acc1.w = fmaf(c1, w.w, acc1.w);
                acc2.x = fmaf(c2, w.x, acc2.x); acc2.y = fmaf(c2, w.y, acc2.y);
                acc2.z = fmaf(c2, w.z, acc2.z); acc2.w = fmaf(c2, w.w, acc2.w);
                acc3.x = fmaf(c3, w.x, acc3.x); acc3.y = fmaf(c3, w.y, acc3.y);
                acc3.z = fmaf(c3, w.z, acc3.z); acc3.w = fmaf(c3, w.w, acc3.w);
            }
        }

        // epilogue: bias, NodeNorm (mean/var over the 128 cols spread across
        // the warp as 4 per lane), relu, residual, store.
        float4 accs[4] = {acc0, acc1, acc2, acc3};
        #pragma unroll
        for (int r = 0; r < 4; r++) {
            int row = base + r;
            if (row >= N) break;
            float4 h = accs[r];
            h.x += bv.x; h.y += bv.y; h.z += bv.z; h.w += bv.w;
            float s  = h.x + h.y + h.z + h.w;
            float ss = h.x * h.x + h.y * h.y + h.z * h.z + h.w * h.w;
            #pragma unroll
            for (int off = 16; off > 0; off >>= 1) {
                s  += __shfl_xor_sync(0xffffffffu, s, off);
                ss += __shfl_xor_sync(0xffffffffu, ss, off);
            }
            float mean = s * (1.0f / DIMF);
            float var = ss * (1.0f / DIMF) - mean * mean;
            float inv = rsqrtf(var + 1e-5f);
            float4 xv = x4[row * (DIMF / 4) + lane];
            float4 o;
            o.x = fmaxf((h.x - mean) * inv, 0.f) + xv.x;
            o.y = fmaxf((h.y - mean) * inv, 0.f) + xv.y;
            o.z = fmaxf((h.z - mean) * inv, 0.f) + xv.z;
            o.w = fmaxf((h.w - mean) * inv, 0.f) + xv.w;
            out4[row * (DIMF / 4) + lane] = o;
        }
        __syncwarp();
    }
}

// ---------------------------------------------------------------------------
// launch
// ---------------------------------------------------------------------------
extern "C" void kernel_launch(void* const* d_in, const int* in_sizes, int n_in,
                              void* d_out, int out_size) {
    const float* x      = (const float*)d_in[0];
    const float* weight = (const float*)d_in[1];
    const float* bias   = (const float*)d_in[2];
    const int*   src    = (const int*)d_in[3];
    const int*   dst    = (const int*)d_in[4];
    float* out = (float*)d_out;

    const int N = in_sizes[0] / DIMF;
    const int E = in_sizes[3];
    if (N > MAXN) return;  // scratch sized for the dataset's fixed N

    cudaFuncSetAttribute(gemm_norm_kernel,
                         cudaFuncAttributeMaxDynamicSharedMemorySize,
                         GEMM_SMEM_BYTES);

    const float4* x4 = (const float4*)x;

    zero_kernel<<<(N * (DIMF / 4) + 255) / 256, 256>>>(N);
    deg_kernel<<<(E + 255) / 256, 256>>>(src, dst, E);
    agg_kernel<<<(E + 7) / 8, 256>>>(x4, src, dst, E);
    gemm_norm_kernel<<<296, 256, GEMM_SMEM_BYTES>>>(x4, weight, bias, (float4*)out, N);
}